// round 15
// baseline (speedup 1.0000x reference)
#include <cuda_runtime.h>
#include <cuda_bf16.h>
#include <cstdint>

#define ST 144                  // row stride bytes (72 bf16): bank-rotating, 16B-aligned
#define ADJ_O 0                 // adjacency -> h3 hi
#define XH_O  9216              // X^T hi / T hi / h3 lo
#define XL_O  18432             // X^T lo / T lo / head: Wf1^T half1 hi
#define WH_O  27648             // W^T hi (emb: obs hi cols0-63 + embW hi cols64-127; head: Wf1^T half0 hi -> half1 lo)
#define WL_O  36864             // W^T lo (emb: obs lo + embW lo; head: Wf1^T half0 lo)
#define MLO_O  46080
#define MHI_O  46336
#define DINV_O 46592
#define BIAS_O 46848
#define U_O    47104
#define WF2_O  47616
#define MEAN_O 48128
#define H3S_O  48384
#define PART_O 48640            // float[2][64]
#define CS_O   49152            // emb biases (bd|bs) -> col-sums -> u partials
#define SMEM_BYTES 50176

static __device__ __align__(16) unsigned char g_WT[3][2][9216];   // W_L^T [n][k] hi/lo
static __device__ __align__(16) unsigned char g_Wf1T[2][18432];   // Wf1_dev^T [m][k] hi/lo
static __device__ __align__(16) unsigned char g_embWT[2][4096];   // combined emb W^T [c][k<32] hi/lo (64B rows)

__device__ __forceinline__ uint32_t smem_u32(const void* p) {
    uint32_t a;
    asm("{ .reg .u64 t; cvta.to.shared.u64 t, %1; cvt.u32.u64 %0, t; }" : "=r"(a) : "l"(p));
    return a;
}
__device__ __forceinline__ void ldsm4(uint32_t addr, uint32_t* r) {
    asm volatile("ldmatrix.sync.aligned.m8n8.x4.shared.b16 {%0,%1,%2,%3}, [%4];"
                 : "=r"(r[0]), "=r"(r[1]), "=r"(r[2]), "=r"(r[3]) : "r"(addr));
}
__device__ __forceinline__ void mma16816(float* d, const uint32_t* a, const uint32_t* b) {
    asm volatile("mma.sync.aligned.m16n8k16.row.col.f32.bf16.bf16.f32 "
        "{%0,%1,%2,%3}, {%4,%5,%6,%7}, {%8,%9}, {%0,%1,%2,%3};"
        : "+f"(d[0]), "+f"(d[1]), "+f"(d[2]), "+f"(d[3])
        : "r"(a[0]), "r"(a[1]), "r"(a[2]), "r"(a[3]), "r"(b[0]), "r"(b[1]));
}
__device__ __forceinline__ void sp1(float v, uint16_t& h, uint16_t& l) {
    __nv_bfloat16 hb = __float2bfloat16(v);
    __nv_bfloat16 lb = __float2bfloat16(v - __bfloat162float(hb));
    h = __bfloat16_as_ushort(hb); l = __bfloat16_as_ushort(lb);
}
// pack (a,b) -> hi bf16x2 + residual lo bf16x2
__device__ __forceinline__ uint32_t sp2(float a, float b, uint32_t& lo) {
    uint32_t hi;
    asm("cvt.rn.bf16x2.f32 %0, %1, %2;" : "=r"(hi) : "f"(b), "f"(a));
    float ha = __uint_as_float(hi << 16);
    float hb = __uint_as_float(hi & 0xffff0000u);
    asm("cvt.rn.bf16x2.f32 %0, %1, %2;" : "=r"(lo) : "f"(b - hb), "f"(a - ha));
    return hi;
}
// acc += A@B1^T + A@B2^T (A loaded once). Both B ldsm batched before mma for MLP.
__device__ __forceinline__ void gprod_dualB(uint32_t aB, uint32_t b1B, uint32_t b2B,
                                            int lane, float (*acc)[4]) {
    const int arow = lane & 15, acol = (lane >> 4) << 3;
    const int brow = (lane & 7) + ((lane & 16) >> 1), bcol = lane & 8;
    #pragma unroll
    for (int kk = 0; kk < 64; kk += 16) {
        uint32_t a[4]; ldsm4(aB + arow * ST + (kk + acol) * 2, a);
        #pragma unroll
        for (int nt = 0; nt < 2; nt++) {
            uint32_t bf1[4], bf2[4];
            ldsm4(b1B + (nt * 16 + brow) * ST + (kk + bcol) * 2, bf1);
            ldsm4(b2B + (nt * 16 + brow) * ST + (kk + bcol) * 2, bf2);
            mma16816(acc[nt * 2], a, bf1);
            mma16816(acc[nt * 2 + 1], a, bf1 + 2);
            mma16816(acc[nt * 2], a, bf2);
            mma16816(acc[nt * 2 + 1], a, bf2 + 2);
        }
    }
}
// acc += A1@B1^T + A1@B2^T + A2@B1^T — fragments loaded once; B ldsm batched; K=64
__device__ __forceinline__ void gprod_tri(uint32_t a1B, uint32_t a2B,
                                          uint32_t b1B, uint32_t b2B,
                                          int lane, float (*acc)[4]) {
    const int arow = lane & 15, acol = (lane >> 4) << 3;
    const int brow = (lane & 7) + ((lane & 16) >> 1), bcol = lane & 8;
    #pragma unroll
    for (int kk = 0; kk < 64; kk += 16) {
        uint32_t a0[4], a1[4];
        ldsm4(a1B + arow * ST + (kk + acol) * 2, a0);
        ldsm4(a2B + arow * ST + (kk + acol) * 2, a1);
        #pragma unroll
        for (int nt = 0; nt < 2; nt++) {
            uint32_t bf1[4], bf2[4];
            ldsm4(b1B + (nt * 16 + brow) * ST + (kk + bcol) * 2, bf1);
            ldsm4(b2B + (nt * 16 + brow) * ST + (kk + bcol) * 2, bf2);
            mma16816(acc[nt * 2], a0, bf1);
            mma16816(acc[nt * 2 + 1], a0, bf1 + 2);
            mma16816(acc[nt * 2], a1, bf1);
            mma16816(acc[nt * 2 + 1], a1, bf1 + 2);
            mma16816(acc[nt * 2], a0, bf2);
            mma16816(acc[nt * 2 + 1], a0, bf2 + 2);
        }
    }
}
// same, K=32 (embedding)
__device__ __forceinline__ void gprod_tri32(uint32_t a1B, uint32_t a2B,
                                            uint32_t b1B, uint32_t b2B,
                                            int lane, float (*acc)[4]) {
    const int arow = lane & 15, acol = (lane >> 4) << 3;
    const int brow = (lane & 7) + ((lane & 16) >> 1), bcol = lane & 8;
    #pragma unroll
    for (int kk = 0; kk < 32; kk += 16) {
        uint32_t a0[4], a1[4];
        ldsm4(a1B + arow * ST + (kk + acol) * 2, a0);
        ldsm4(a2B + arow * ST + (kk + acol) * 2, a1);
        #pragma unroll
        for (int nt = 0; nt < 2; nt++) {
            uint32_t bf1[4], bf2[4];
            ldsm4(b1B + (nt * 16 + brow) * ST + (kk + bcol) * 2, bf1);
            ldsm4(b2B + (nt * 16 + brow) * ST + (kk + bcol) * 2, bf2);
            mma16816(acc[nt * 2], a0, bf1);
            mma16816(acc[nt * 2 + 1], a0, bf1 + 2);
            mma16816(acc[nt * 2], a1, bf1);
            mma16816(acc[nt * 2 + 1], a1, bf1 + 2);
            mma16816(acc[nt * 2], a0, bf2);
            mma16816(acc[nt * 2 + 1], a0, bf2 + 2);
        }
    }
}

__global__ void pgcn_prep(const float* __restrict__ W1, const float* __restrict__ W2,
                          const float* __restrict__ W3, const float* __restrict__ Wf1,
                          const float* __restrict__ W_dev, const float* __restrict__ W_srv) {
    const float* Ws[3] = {W1, W2, W3};
    int gt = blockIdx.x * blockDim.x + threadIdx.x, nth = gridDim.x * blockDim.x;
    for (int L = 0; L < 3; L++)
        for (int i = gt; i < 4096; i += nth) {
            int n = i >> 6, k = i & 63;
            uint16_t h, l; sp1(Ws[L][k * 64 + n], h, l);
            *(uint16_t*)(g_WT[L][0] + n * ST + k * 2) = h;
            *(uint16_t*)(g_WT[L][1] + n * ST + k * 2) = l;
        }
    for (int i = gt; i < 8192; i += nth) {
        int m = i >> 6, k = i & 63;
        uint16_t h, l; sp1(Wf1[k * 128 + m], h, l);
        *(uint16_t*)(g_Wf1T[0] + m * ST + k * 2) = h;
        *(uint16_t*)(g_Wf1T[1] + m * ST + k * 2) = l;
    }
    for (int i = gt; i < 2048; i += nth) {
        int c = i >> 5, k = i & 31;
        float v = (k < 14) ? W_dev[k * 64 + c] : (k < 17 ? W_srv[(k - 14) * 64 + c] : 0.0f);
        uint16_t h, l; sp1(v, h, l);
        *(uint16_t*)(g_embWT[0] + c * 64 + k * 2) = h;
        *(uint16_t*)(g_embWT[1] + c * 64 + k * 2) = l;
    }
}

__global__ __launch_bounds__(256, 4)
void pgcn_main(const float* __restrict__ dev_obs, const float* __restrict__ srv_obs,
               const float* __restrict__ adj,
               const float* __restrict__ b_dev, const float* __restrict__ b_srv,
               const float* __restrict__ b1, const float* __restrict__ b2,
               const float* __restrict__ b3,
               const float* __restrict__ Wf1, const float* __restrict__ bf1,
               const float* __restrict__ Wf2, const float* __restrict__ bf2,
               float* __restrict__ out)
{
    extern __shared__ __align__(16) unsigned char sm[];
    const uint32_t sb = smem_u32(sm);
    unsigned* s_mlo = (unsigned*)(sm + MLO_O);
    unsigned* s_mhi = (unsigned*)(sm + MHI_O);
    float* s_dinv = (float*)(sm + DINV_O);
    float* s_bias = (float*)(sm + BIAS_O);
    float* s_u    = (float*)(sm + U_O);
    float* s_wf2  = (float*)(sm + WF2_O);
    float* s_mean = (float*)(sm + MEAN_O);
    float* s_h3s  = (float*)(sm + H3S_O);
    float* s_part = (float*)(sm + PART_O);
    float* s_cs   = (float*)(sm + CS_O);

    const int tid = threadIdx.x, lane = tid & 31, wid = tid >> 5;
    const int b = blockIdx.x;
    const int m0 = (wid & 3) * 16, ch2 = wid >> 2, n0 = ch2 * 32;
    const int g = lane >> 2, c0b = (lane & 3) * 2;

    // ---- stage obs bf16 tiles, embW, emb biases, masks + dinv ----
    if (tid < 64) {
        int n = tid;
        float v[32];
        #pragma unroll
        for (int k = 0; k < 32; k++) v[k] = 0.0f;
        if (n < 63) {
            const float* o = dev_obs + (size_t)b * 882 + n * 14;
            #pragma unroll
            for (int k = 0; k < 14; k++) v[k] = o[k];
        } else {
            #pragma unroll
            for (int k = 0; k < 3; k++) v[14 + k] = srv_obs[b * 3 + k];
        }
        #pragma unroll
        for (int j = 0; j < 16; j++) {
            uint32_t lo, hi = sp2(v[2 * j], v[2 * j + 1], lo);
            *(uint32_t*)(sm + WH_O + n * ST + j * 4) = hi;
            *(uint32_t*)(sm + WL_O + n * ST + j * 4) = lo;
        }
    } else if (tid < 128) {
        int i0 = tid - 64;
        for (int i = i0; i < 256; i += 64) {
            int row = i >> 2, q = i & 3;
            *(uint4*)(sm + WH_O + row * ST + 64 + q * 16) =
                *(const uint4*)(g_embWT[0] + row * 64 + q * 16);
            *(uint4*)(sm + WL_O + row * ST + 64 + q * 16) =
                *(const uint4*)(g_embWT[1] + row * 64 + q * 16);
        }
    } else if (tid < 192) {
        int i = tid - 128;
        s_cs[i] = b_dev[i];
        s_cs[64 + i] = b_srv[i];
    }
    {
        const float* ar = adj + (size_t)b * 4096;
        for (int r = wid; r < 64; r += 8) {
            unsigned a0 = __ballot_sync(0xffffffffu, ar[r * 64 + lane] != 0.0f);
            unsigned a1 = __ballot_sync(0xffffffffu, ar[r * 64 + 32 + lane] != 0.0f);
            if (lane == 0) {
                s_mlo[r] = a0; s_mhi[r] = a1;
                s_dinv[r] = rsqrtf(fmaxf((float)(__popc(a0) + __popc(a1)), 1.0f));
            }
        }
    }
    __syncthreads();

    // ---- adjacency bf16 tile ----
    for (int i = tid; i < 512; i += 256) {
        int r = i >> 3, chk = i & 7;
        unsigned byte8 = ((chk < 4 ? s_mlo[r] : s_mhi[r]) >> ((chk & 3) * 8)) & 0xFF;
        uint4 v; uint32_t* vp = (uint32_t*)&v;
        #pragma unroll
        for (int j = 0; j < 4; j++) {
            unsigned b2 = (byte8 >> (2 * j)) & 3;
            vp[j] = ((b2 & 1) ? 0x3F80u : 0u) | ((b2 & 2) ? 0x3F800000u : 0u);
        }
        *(uint4*)(sm + ADJ_O + r * ST + chk * 16) = v;
    }
    // ---- embedding GEMM: D[c][n] = embW @ obs^T (tri-fused split, K=32) ----
    {
        float acc[4][4];
        #pragma unroll
        for (int i = 0; i < 4; i++) { acc[i][0]=acc[i][1]=acc[i][2]=acc[i][3]=0.f; }
        gprod_tri32(sb + WH_O + 64 + m0 * ST, sb + WL_O + 64 + m0 * ST,
                    sb + WH_O + n0 * ST, sb + WL_O + n0 * ST, lane, acc);
        const int cA0 = m0 + g, cA1 = cA0 + 8;
        float bd0 = s_cs[cA0], bd1 = s_cs[cA1];
        float bs0 = s_cs[64 + cA0], bs1 = s_cs[64 + cA1];
        #pragma unroll
        for (int nt = 0; nt < 4; nt++) {
            int r0 = n0 + nt * 8 + c0b;
            float da = s_dinv[r0], db = s_dinv[r0 + 1];
            float bb0a = (r0 == 63) ? bs0 : bd0, bb0b = (r0 + 1 == 63) ? bs0 : bd0;
            float bb1a = (r0 == 63) ? bs1 : bd1, bb1b = (r0 + 1 == 63) ? bs1 : bd1;
            uint32_t lo, hi;
            hi = sp2(fmaxf(acc[nt][0] + bb0a, 0.f) * da,
                     fmaxf(acc[nt][1] + bb0b, 0.f) * db, lo);
            *(uint32_t*)(sm + XH_O + cA0 * ST + r0 * 2) = hi;
            *(uint32_t*)(sm + XL_O + cA0 * ST + r0 * 2) = lo;
            hi = sp2(fmaxf(acc[nt][2] + bb1a, 0.f) * da,
                     fmaxf(acc[nt][3] + bb1b, 0.f) * db, lo);
            *(uint32_t*)(sm + XH_O + cA1 * ST + r0 * 2) = hi;
            *(uint32_t*)(sm + XL_O + cA1 * ST + r0 * 2) = lo;
        }
    }
    __syncthreads();

    // ---- 3 GCN layers ----
    #pragma unroll 1
    for (int L = 0; L < 3; L++) {
        {   // stage W^T hi/lo + bias
            const uint4* wh = (const uint4*)g_WT[L][0];
            const uint4* wl = (const uint4*)g_WT[L][1];
            for (int i = tid; i < 576; i += 256) {
                ((uint4*)(sm + WH_O))[i] = wh[i];
                ((uint4*)(sm + WL_O))[i] = wl[i];
            }
            const float* bl = (L == 0) ? b1 : (L == 1) ? b2 : b3;
            if (tid < 64) s_bias[tid] = bl[tid];
        }
        // aggregation: D[r][c] = Adj @ (XH + XL)^T
        float acc[4][4];
        #pragma unroll
        for (int i = 0; i < 4; i++) { acc[i][0]=acc[i][1]=acc[i][2]=acc[i][3]=0.f; }
        gprod_dualB(sb + ADJ_O + m0 * ST, sb + XH_O + n0 * ST, sb + XL_O + n0 * ST, lane, acc);
        __syncthreads();   // all X reads done; W staged

        // epi1: T[r][c] = dinv[r]*D -> overwrite XH/XL (T tiles)
        {
            const int r0 = m0 + g, r1 = r0 + 8;
            float d0 = s_dinv[r0], d1 = s_dinv[r1];
            #pragma unroll
            for (int nt = 0; nt < 4; nt++) {
                int c0 = n0 + nt * 8 + c0b;
                uint32_t lo, hi;
                hi = sp2(acc[nt][0] * d0, acc[nt][1] * d0, lo);
                *(uint32_t*)(sm + XH_O + r0 * ST + c0 * 2) = hi;
                *(uint32_t*)(sm + XL_O + r0 * ST + c0 * 2) = lo;
                hi = sp2(acc[nt][2] * d1, acc[nt][3] * d1, lo);
                *(uint32_t*)(sm + XH_O + r1 * ST + c0 * 2) = hi;
                *(uint32_t*)(sm + XL_O + r1 * ST + c0 * 2) = lo;
            }
        }
        __syncthreads();   // T visible

        #pragma unroll
        for (int i = 0; i < 4; i++) { acc[i][0]=acc[i][1]=acc[i][2]=acc[i][3]=0.f; }
        if (L < 2) {
            // gemm (transposed out): D[c][r] = Whi·(Thi+Tlo) + Wlo·Thi (tri-fused)
            gprod_tri(sb + WH_O + m0 * ST, sb + WL_O + m0 * ST,
                      sb + XH_O + n0 * ST, sb + XL_O + n0 * ST, lane, acc);
            __syncthreads();   // all T reads done
            // epi2: X^T[c][r] = relu(D + b[c]) * dinv[r]
            const int cA0 = m0 + g, cA1 = cA0 + 8;
            float bA0 = s_bias[cA0], bA1 = s_bias[cA1];
            #pragma unroll
            for (int nt = 0; nt < 4; nt++) {
                int r0 = n0 + nt * 8 + c0b;
                float da = s_dinv[r0], db = s_dinv[r0 + 1];
                uint32_t lo, hi;
                hi = sp2(fmaxf(acc[nt][0] + bA0, 0.f) * da,
                         fmaxf(acc[nt][1] + bA0, 0.f) * db, lo);
                *(uint32_t*)(sm + XH_O + cA0 * ST + r0 * 2) = hi;
                *(uint32_t*)(sm + XL_O + cA0 * ST + r0 * 2) = lo;
                hi = sp2(fmaxf(acc[nt][2] + bA1, 0.f) * da,
                         fmaxf(acc[nt][3] + bA1, 0.f) * db, lo);
                *(uint32_t*)(sm + XH_O + cA1 * ST + r0 * 2) = hi;
                *(uint32_t*)(sm + XL_O + cA1 * ST + r0 * 2) = lo;
            }
        } else {
            // gemm3: D[r][c] = (Thi+Tlo)·Whi + Thi·Wlo  (node-major h3, tri-fused)
            gprod_tri(sb + XH_O + m0 * ST, sb + XL_O + m0 * ST,
                      sb + WH_O + n0 * ST, sb + WL_O + n0 * ST, lane, acc);
            __syncthreads();
            // epi3: h3 = relu(D + b[c]); hi->ADJ, lo->XH; col-sums + server row
            const int r0 = m0 + g, r1 = r0 + 8;
            const bool srvlane = (m0 == 48) && (g == 7);   // r1 == 63
            float csA[4], csB[4];
            #pragma unroll
            for (int nt = 0; nt < 4; nt++) {
                int c0 = n0 + nt * 8 + c0b;
                float b0v = s_bias[c0], b1v = s_bias[c0 + 1];
                float v0 = fmaxf(acc[nt][0] + b0v, 0.f);
                float v1 = fmaxf(acc[nt][1] + b1v, 0.f);
                float v2 = fmaxf(acc[nt][2] + b0v, 0.f);
                float v3 = fmaxf(acc[nt][3] + b1v, 0.f);
                uint32_t lo, hi;
                hi = sp2(v0, v1, lo);
                *(uint32_t*)(sm + ADJ_O + r0 * ST + c0 * 2) = hi;
                *(uint32_t*)(sm + XH_O + r0 * ST + c0 * 2) = lo;
                hi = sp2(v2, v3, lo);
                *(uint32_t*)(sm + ADJ_O + r1 * ST + c0 * 2) = hi;
                *(uint32_t*)(sm + XH_O + r1 * ST + c0 * 2) = lo;
                csA[nt] = v0 + (srvlane ? 0.f : v2);
                csB[nt] = v1 + (srvlane ? 0.f : v3);
                if (srvlane) { s_h3s[c0] = v2; s_h3s[c0 + 1] = v3; }
            }
            #pragma unroll
            for (int off = 4; off < 32; off <<= 1) {
                #pragma unroll
                for (int nt = 0; nt < 4; nt++) {
                    csA[nt] += __shfl_xor_sync(0xffffffffu, csA[nt], off);
                    csB[nt] += __shfl_xor_sync(0xffffffffu, csB[nt], off);
                }
            }
            if (g == 0) {
                float* cs = s_cs + (m0 >> 4) * 64;
                #pragma unroll
                for (int nt = 0; nt < 4; nt++) {
                    int c0 = n0 + nt * 8 + c0b;
                    cs[c0] = csA[nt]; cs[c0 + 1] = csB[nt];
                }
            }
        }
        __syncthreads();
    }

    // ---- P1: mean from col-sums || stage Wf1^T half0 hi/lo + half1 hi + wf2 ----
    if (tid < 64) {
        s_mean[tid] = (s_cs[tid] + s_cs[64 + tid] + s_cs[128 + tid] + s_cs[192 + tid])
                      * (1.0f / 63.0f);
    } else {
        const uint4* hh = (const uint4*)g_Wf1T[0];
        const uint4* hl = (const uint4*)g_Wf1T[1];
        for (int i = tid - 64; i < 576; i += 192) {
            ((uint4*)(sm + WH_O))[i] = hh[i];
            ((uint4*)(sm + WL_O))[i] = hl[i];
            ((uint4*)(sm + XL_O))[i] = hh[576 + i];   // half1 hi pre-staged
        }
        if (tid - 64 < 128) s_wf2[tid - 64] = Wf2[tid - 64];
    }
    __syncthreads();
    {   // u partials: 256 threads, half the k-range each (overlays s_cs)
        int m = tid & 127, half = tid >> 7, k0 = half * 32;
        float acc = 0.0f;
        #pragma unroll 4
        for (int k = k0; k < k0 + 32; k++) acc = fmaf(s_mean[k], Wf1[(64 + k) * 128 + m], acc);
        #pragma unroll 4
        for (int k = k0; k < k0 + 32; k++) acc = fmaf(s_h3s[k], Wf1[(128 + k) * 128 + m], acc);
        s_cs[tid] = acc;
    }
    __syncthreads();
    if (tid < 128) s_u[tid] = bf1[tid] + s_cs[tid] + s_cs[128 + tid];
    __syncthreads();

    // ---- head GEMM half 0 (B = WH/WL, tri-fused) ----
    float p0 = 0.f, p1 = 0.f;
    {
        float acc[4][4];
        #pragma unroll
        for (int i = 0; i < 4; i++) { acc[i][0]=acc[i][1]=acc[i][2]=acc[i][3]=0.f; }
        gprod_tri(sb + ADJ_O + m0 * ST, sb + XH_O + m0 * ST,
                  sb + WH_O + n0 * ST, sb + WL_O + n0 * ST, lane, acc);
        #pragma unroll
        for (int nt = 0; nt < 4; nt++) {
            int c0 = n0 + nt * 8 + c0b;
            float u0 = s_u[c0], u1 = s_u[c0 + 1], w0 = s_wf2[c0], w1 = s_wf2[c0 + 1];
            p0 = fmaf(fmaxf(acc[nt][0] + u0, 0.f), w0, p0);
            p0 = fmaf(fmaxf(acc[nt][1] + u1, 0.f), w1, p0);
            p1 = fmaf(fmaxf(acc[nt][2] + u0, 0.f), w0, p1);
            p1 = fmaf(fmaxf(acc[nt][3] + u1, 0.f), w1, p1);
        }
    }
    __syncthreads();   // WH reads done
    {   // stage half1 lo into WH (9KB)
        const uint4* hl = (const uint4*)(g_Wf1T[1] + 9216);
        for (int i = tid; i < 576; i += 256) ((uint4*)(sm + WH_O))[i] = hl[i];
    }
    __syncthreads();
    // ---- head GEMM half 1 (B hi = XL pre-staged, lo = WH, tri-fused) ----
    {
        float acc[4][4];
        #pragma unroll
        for (int i = 0; i < 4; i++) { acc[i][0]=acc[i][1]=acc[i][2]=acc[i][3]=0.f; }
        gprod_tri(sb + ADJ_O + m0 * ST, sb + XH_O + m0 * ST,
                  sb + XL_O + n0 * ST, sb + WH_O + n0 * ST, lane, acc);
        #pragma unroll
        for (int nt = 0; nt < 4; nt++) {
            int c0 = 64 + n0 + nt * 8 + c0b;
            float u0 = s_u[c0], u1 = s_u[c0 + 1], w0 = s_wf2[c0], w1 = s_wf2[c0 + 1];
            p0 = fmaf(fmaxf(acc[nt][0] + u0, 0.f), w0, p0);
            p0 = fmaf(fmaxf(acc[nt][1] + u1, 0.f), w1, p0);
            p1 = fmaf(fmaxf(acc[nt][2] + u0, 0.f), w0, p1);
            p1 = fmaf(fmaxf(acc[nt][3] + u1, 0.f), w1, p1);
        }
    }
    p0 += __shfl_xor_sync(0xffffffffu, p0, 1); p0 += __shfl_xor_sync(0xffffffffu, p0, 2);
    p1 += __shfl_xor_sync(0xffffffffu, p1, 1); p1 += __shfl_xor_sync(0xffffffffu, p1, 2);
    if ((lane & 3) == 0) {
        s_part[ch2 * 64 + m0 + g] = p0;
        s_part[ch2 * 64 + m0 + g + 8] = p1;
    }
    __syncthreads();
    if (tid < 63) out[(size_t)b * 63 + tid] = s_part[tid] + s_part[64 + tid] + bf2[0];
}

extern "C" void kernel_launch(void* const* d_in, const int* in_sizes, int n_in,
                              void* d_out, int out_size)
{
    (void)in_sizes; (void)n_in; (void)out_size;
    cudaFuncSetAttribute(pgcn_main, cudaFuncAttributeMaxDynamicSharedMemorySize, SMEM_BYTES);
    pgcn_prep<<<64, 256>>>((const float*)d_in[7], (const float*)d_in[9],
                           (const float*)d_in[11], (const float*)d_in[13],
                           (const float*)d_in[3], (const float*)d_in[5]);
    pgcn_main<<<16384, 256, SMEM_BYTES>>>(
        (const float*)d_in[0],  (const float*)d_in[1],  (const float*)d_in[2],
        (const float*)d_in[4],  (const float*)d_in[6],  (const float*)d_in[8],
        (const float*)d_in[10], (const float*)d_in[12], (const float*)d_in[13],
        (const float*)d_in[14], (const float*)d_in[15], (const float*)d_in[16],
        (float*)d_out);
}

// round 16
// speedup vs baseline: 1.1221x; 1.1221x over previous
#include <cuda_runtime.h>
#include <cuda_bf16.h>
#include <cstdint>

#define ST 144                  // row stride bytes (72 bf16): bank-rotating, 16B-aligned
#define ADJ_O 0                 // adjacency -> h3 hi
#define XH_O  9216              // X^T hi / T hi / h3 lo
#define XL_O  18432             // X^T lo / T lo / head: Wf1^T half1 hi
#define WH_O  27648             // W^T hi (emb: obs hi cols0-63 + embW hi cols64-127; head: Wf1^T half0 hi -> half1 lo)
#define WL_O  36864             // W^T lo (emb: obs lo + embW lo; head: Wf1^T half0 lo)
#define MLO_O  46080
#define MHI_O  46336
#define DINV_O 46592
#define BIAS_O 46848
#define U_O    47104
#define WF2_O  47616
#define MEAN_O 48128
#define H3S_O  48384
#define PART_O 48640            // float[2][64]
#define CS_O   49152            // emb biases (bd|bs) -> col-sums -> u partials
#define SMEM_BYTES 50176

static __device__ __align__(16) unsigned char g_WT[3][2][9216];   // W_L^T [n][k] hi/lo
static __device__ __align__(16) unsigned char g_Wf1T[2][18432];   // Wf1_dev^T [m][k] hi/lo
static __device__ __align__(16) unsigned char g_embWT[2][4096];   // combined emb W^T [c][k<32] hi/lo (64B rows)

__device__ __forceinline__ uint32_t smem_u32(const void* p) {
    uint32_t a;
    asm("{ .reg .u64 t; cvta.to.shared.u64 t, %1; cvt.u32.u64 %0, t; }" : "=r"(a) : "l"(p));
    return a;
}
__device__ __forceinline__ void cpa16(uint32_t dst, const void* src) {
    asm volatile("cp.async.cg.shared.global [%0], [%1], 16;" :: "r"(dst), "l"(src));
}
#define CP_COMMIT() asm volatile("cp.async.commit_group;" ::: "memory")
#define CP_WAIT0()  asm volatile("cp.async.wait_group 0;" ::: "memory")

__device__ __forceinline__ void ldsm4(uint32_t addr, uint32_t* r) {
    asm volatile("ldmatrix.sync.aligned.m8n8.x4.shared.b16 {%0,%1,%2,%3}, [%4];"
                 : "=r"(r[0]), "=r"(r[1]), "=r"(r[2]), "=r"(r[3]) : "r"(addr));
}
__device__ __forceinline__ void mma16816(float* d, const uint32_t* a, const uint32_t* b) {
    asm volatile("mma.sync.aligned.m16n8k16.row.col.f32.bf16.bf16.f32 "
        "{%0,%1,%2,%3}, {%4,%5,%6,%7}, {%8,%9}, {%0,%1,%2,%3};"
        : "+f"(d[0]), "+f"(d[1]), "+f"(d[2]), "+f"(d[3])
        : "r"(a[0]), "r"(a[1]), "r"(a[2]), "r"(a[3]), "r"(b[0]), "r"(b[1]));
}
__device__ __forceinline__ void sp1(float v, uint16_t& h, uint16_t& l) {
    __nv_bfloat16 hb = __float2bfloat16(v);
    __nv_bfloat16 lb = __float2bfloat16(v - __bfloat162float(hb));
    h = __bfloat16_as_ushort(hb); l = __bfloat16_as_ushort(lb);
}
__device__ __forceinline__ uint32_t sp2(float a, float b, uint32_t& lo) {
    uint32_t hi;
    asm("cvt.rn.bf16x2.f32 %0, %1, %2;" : "=r"(hi) : "f"(b), "f"(a));
    float ha = __uint_as_float(hi << 16);
    float hb = __uint_as_float(hi & 0xffff0000u);
    asm("cvt.rn.bf16x2.f32 %0, %1, %2;" : "=r"(lo) : "f"(b - hb), "f"(a - ha));
    return hi;
}
// acc += A@B1^T + A@B2^T (A loaded once)
__device__ __forceinline__ void gprod_dualB(uint32_t aB, uint32_t b1B, uint32_t b2B,
                                            int lane, float (*acc)[4]) {
    const int arow = lane & 15, acol = (lane >> 4) << 3;
    const int brow = (lane & 7) + ((lane & 16) >> 1), bcol = lane & 8;
    #pragma unroll
    for (int kk = 0; kk < 64; kk += 16) {
        uint32_t a[4]; ldsm4(aB + arow * ST + (kk + acol) * 2, a);
        #pragma unroll
        for (int nt = 0; nt < 2; nt++) {
            uint32_t bf1[4], bf2[4];
            ldsm4(b1B + (nt * 16 + brow) * ST + (kk + bcol) * 2, bf1);
            ldsm4(b2B + (nt * 16 + brow) * ST + (kk + bcol) * 2, bf2);
            mma16816(acc[nt * 2], a, bf1);
            mma16816(acc[nt * 2 + 1], a, bf1 + 2);
            mma16816(acc[nt * 2], a, bf2);
            mma16816(acc[nt * 2 + 1], a, bf2 + 2);
        }
    }
}
// acc += A1@B1^T + A1@B2^T + A2@B1^T — fragments loaded once; K=64
__device__ __forceinline__ void gprod_tri(uint32_t a1B, uint32_t a2B,
                                          uint32_t b1B, uint32_t b2B,
                                          int lane, float (*acc)[4]) {
    const int arow = lane & 15, acol = (lane >> 4) << 3;
    const int brow = (lane & 7) + ((lane & 16) >> 1), bcol = lane & 8;
    #pragma unroll
    for (int kk = 0; kk < 64; kk += 16) {
        uint32_t a0[4], a1[4];
        ldsm4(a1B + arow * ST + (kk + acol) * 2, a0);
        ldsm4(a2B + arow * ST + (kk + acol) * 2, a1);
        #pragma unroll
        for (int nt = 0; nt < 2; nt++) {
            uint32_t bf1[4], bf2[4];
            ldsm4(b1B + (nt * 16 + brow) * ST + (kk + bcol) * 2, bf1);
            ldsm4(b2B + (nt * 16 + brow) * ST + (kk + bcol) * 2, bf2);
            mma16816(acc[nt * 2], a0, bf1);
            mma16816(acc[nt * 2 + 1], a0, bf1 + 2);
            mma16816(acc[nt * 2], a1, bf1);
            mma16816(acc[nt * 2 + 1], a1, bf1 + 2);
            mma16816(acc[nt * 2], a0, bf2);
            mma16816(acc[nt * 2 + 1], a0, bf2 + 2);
        }
    }
}
// same, K=32 (embedding)
__device__ __forceinline__ void gprod_tri32(uint32_t a1B, uint32_t a2B,
                                            uint32_t b1B, uint32_t b2B,
                                            int lane, float (*acc)[4]) {
    const int arow = lane & 15, acol = (lane >> 4) << 3;
    const int brow = (lane & 7) + ((lane & 16) >> 1), bcol = lane & 8;
    #pragma unroll
    for (int kk = 0; kk < 32; kk += 16) {
        uint32_t a0[4], a1[4];
        ldsm4(a1B + arow * ST + (kk + acol) * 2, a0);
        ldsm4(a2B + arow * ST + (kk + acol) * 2, a1);
        #pragma unroll
        for (int nt = 0; nt < 2; nt++) {
            uint32_t bf1[4], bf2[4];
            ldsm4(b1B + (nt * 16 + brow) * ST + (kk + bcol) * 2, bf1);
            ldsm4(b2B + (nt * 16 + brow) * ST + (kk + bcol) * 2, bf2);
            mma16816(acc[nt * 2], a0, bf1);
            mma16816(acc[nt * 2 + 1], a0, bf1 + 2);
            mma16816(acc[nt * 2], a1, bf1);
            mma16816(acc[nt * 2 + 1], a1, bf1 + 2);
            mma16816(acc[nt * 2], a0, bf2);
            mma16816(acc[nt * 2 + 1], a0, bf2 + 2);
        }
    }
}

__global__ void pgcn_prep(const float* __restrict__ W1, const float* __restrict__ W2,
                          const float* __restrict__ W3, const float* __restrict__ Wf1,
                          const float* __restrict__ W_dev, const float* __restrict__ W_srv) {
    const float* Ws[3] = {W1, W2, W3};
    int gt = blockIdx.x * blockDim.x + threadIdx.x, nth = gridDim.x * blockDim.x;
    for (int L = 0; L < 3; L++)
        for (int i = gt; i < 4096; i += nth) {
            int n = i >> 6, k = i & 63;
            uint16_t h, l; sp1(Ws[L][k * 64 + n], h, l);
            *(uint16_t*)(g_WT[L][0] + n * ST + k * 2) = h;
            *(uint16_t*)(g_WT[L][1] + n * ST + k * 2) = l;
        }
    for (int i = gt; i < 8192; i += nth) {
        int m = i >> 6, k = i & 63;
        uint16_t h, l; sp1(Wf1[k * 128 + m], h, l);
        *(uint16_t*)(g_Wf1T[0] + m * ST + k * 2) = h;
        *(uint16_t*)(g_Wf1T[1] + m * ST + k * 2) = l;
    }
    for (int i = gt; i < 2048; i += nth) {
        int c = i >> 5, k = i & 31;
        float v = (k < 14) ? W_dev[k * 64 + c] : (k < 17 ? W_srv[(k - 14) * 64 + c] : 0.0f);
        uint16_t h, l; sp1(v, h, l);
        *(uint16_t*)(g_embWT[0] + c * 64 + k * 2) = h;
        *(uint16_t*)(g_embWT[1] + c * 64 + k * 2) = l;
    }
}

__global__ __launch_bounds__(256, 4)
void pgcn_main(const float* __restrict__ dev_obs, const float* __restrict__ srv_obs,
               const float* __restrict__ adj,
               const float* __restrict__ b_dev, const float* __restrict__ b_srv,
               const float* __restrict__ b1, const float* __restrict__ b2,
               const float* __restrict__ b3,
               const float* __restrict__ Wf1, const float* __restrict__ bf1,
               const float* __restrict__ Wf2, const float* __restrict__ bf2,
               float* __restrict__ out)
{
    extern __shared__ __align__(16) unsigned char sm[];
    const uint32_t sb = smem_u32(sm);
    unsigned* s_mlo = (unsigned*)(sm + MLO_O);
    unsigned* s_mhi = (unsigned*)(sm + MHI_O);
    float* s_dinv = (float*)(sm + DINV_O);
    float* s_bias = (float*)(sm + BIAS_O);
    float* s_u    = (float*)(sm + U_O);
    float* s_wf2  = (float*)(sm + WF2_O);
    float* s_mean = (float*)(sm + MEAN_O);
    float* s_h3s  = (float*)(sm + H3S_O);
    float* s_part = (float*)(sm + PART_O);
    float* s_cs   = (float*)(sm + CS_O);

    const int tid = threadIdx.x, lane = tid & 31, wid = tid >> 5;
    const int b = blockIdx.x;
    const int m0 = (wid & 3) * 16, ch2 = wid >> 2, n0 = ch2 * 32;
    const int g = lane >> 2, c0b = (lane & 3) * 2;

    // ---- stage obs bf16 tiles, embW (cp.async), emb biases, masks + dinv ----
    if (tid < 64) {
        int n = tid;
        float v[32];
        #pragma unroll
        for (int k = 0; k < 32; k++) v[k] = 0.0f;
        if (n < 63) {
            const float* o = dev_obs + (size_t)b * 882 + n * 14;
            #pragma unroll
            for (int k = 0; k < 14; k++) v[k] = o[k];
        } else {
            #pragma unroll
            for (int k = 0; k < 3; k++) v[14 + k] = srv_obs[b * 3 + k];
        }
        #pragma unroll
        for (int j = 0; j < 16; j++) {
            uint32_t lo, hi = sp2(v[2 * j], v[2 * j + 1], lo);
            *(uint32_t*)(sm + WH_O + n * ST + j * 4) = hi;
            *(uint32_t*)(sm + WL_O + n * ST + j * 4) = lo;
        }
    } else if (tid < 128) {
        int i0 = tid - 64;
        for (int i = i0; i < 256; i += 64) {
            int row = i >> 2, q = i & 3;
            cpa16(sb + WH_O + row * ST + 64 + q * 16, g_embWT[0] + row * 64 + q * 16);
            cpa16(sb + WL_O + row * ST + 64 + q * 16, g_embWT[1] + row * 64 + q * 16);
        }
    } else if (tid < 192) {
        int i = tid - 128;
        s_cs[i] = b_dev[i];
        s_cs[64 + i] = b_srv[i];
    }
    CP_COMMIT();
    {
        const float* ar = adj + (size_t)b * 4096;
        for (int r = wid; r < 64; r += 8) {
            unsigned a0 = __ballot_sync(0xffffffffu, ar[r * 64 + lane] != 0.0f);
            unsigned a1 = __ballot_sync(0xffffffffu, ar[r * 64 + 32 + lane] != 0.0f);
            if (lane == 0) {
                s_mlo[r] = a0; s_mhi[r] = a1;
                s_dinv[r] = rsqrtf(fmaxf((float)(__popc(a0) + __popc(a1)), 1.0f));
            }
        }
    }
    CP_WAIT0();
    __syncthreads();

    // ---- adjacency bf16 tile ----
    for (int i = tid; i < 512; i += 256) {
        int r = i >> 3, chk = i & 7;
        unsigned byte8 = ((chk < 4 ? s_mlo[r] : s_mhi[r]) >> ((chk & 3) * 8)) & 0xFF;
        uint4 v; uint32_t* vp = (uint32_t*)&v;
        #pragma unroll
        for (int j = 0; j < 4; j++) {
            unsigned b2 = (byte8 >> (2 * j)) & 3;
            vp[j] = ((b2 & 1) ? 0x3F80u : 0u) | ((b2 & 2) ? 0x3F800000u : 0u);
        }
        *(uint4*)(sm + ADJ_O + r * ST + chk * 16) = v;
    }
    // ---- embedding GEMM: D[c][n] = embW @ obs^T (tri-fused split, K=32) ----
    {
        float acc[4][4];
        #pragma unroll
        for (int i = 0; i < 4; i++) { acc[i][0]=acc[i][1]=acc[i][2]=acc[i][3]=0.f; }
        gprod_tri32(sb + WH_O + 64 + m0 * ST, sb + WL_O + 64 + m0 * ST,
                    sb + WH_O + n0 * ST, sb + WL_O + n0 * ST, lane, acc);
        const int cA0 = m0 + g, cA1 = cA0 + 8;
        float bd0 = s_cs[cA0], bd1 = s_cs[cA1];
        float bs0 = s_cs[64 + cA0], bs1 = s_cs[64 + cA1];
        #pragma unroll
        for (int nt = 0; nt < 4; nt++) {
            int r0 = n0 + nt * 8 + c0b;
            float da = s_dinv[r0], db = s_dinv[r0 + 1];
            float bb0a = (r0 == 63) ? bs0 : bd0, bb0b = (r0 + 1 == 63) ? bs0 : bd0;
            float bb1a = (r0 == 63) ? bs1 : bd1, bb1b = (r0 + 1 == 63) ? bs1 : bd1;
            uint32_t lo, hi;
            hi = sp2(fmaxf(acc[nt][0] + bb0a, 0.f) * da,
                     fmaxf(acc[nt][1] + bb0b, 0.f) * db, lo);
            *(uint32_t*)(sm + XH_O + cA0 * ST + r0 * 2) = hi;
            *(uint32_t*)(sm + XL_O + cA0 * ST + r0 * 2) = lo;
            hi = sp2(fmaxf(acc[nt][2] + bb1a, 0.f) * da,
                     fmaxf(acc[nt][3] + bb1b, 0.f) * db, lo);
            *(uint32_t*)(sm + XH_O + cA1 * ST + r0 * 2) = hi;
            *(uint32_t*)(sm + XL_O + cA1 * ST + r0 * 2) = lo;
        }
    }
    __syncthreads();

    // ---- 3 GCN layers ----
    #pragma unroll 1
    for (int L = 0; L < 3; L++) {
        {   // async-stage W^T hi/lo (completes under the agg gprods) + bias
            const unsigned char* wh = g_WT[L][0];
            const unsigned char* wl = g_WT[L][1];
            for (int i = tid; i < 576; i += 256) {
                cpa16(sb + WH_O + i * 16, wh + i * 16);
                cpa16(sb + WL_O + i * 16, wl + i * 16);
            }
            CP_COMMIT();
            const float* bl = (L == 0) ? b1 : (L == 1) ? b2 : b3;
            if (tid < 64) s_bias[tid] = bl[tid];
        }
        // aggregation: D[r][c] = Adj @ (XH + XL)^T
        float acc[4][4];
        #pragma unroll
        for (int i = 0; i < 4; i++) { acc[i][0]=acc[i][1]=acc[i][2]=acc[i][3]=0.f; }
        gprod_dualB(sb + ADJ_O + m0 * ST, sb + XH_O + n0 * ST, sb + XL_O + n0 * ST, lane, acc);
        CP_WAIT0();
        __syncthreads();   // all X reads done; W staged

        // epi1: T[r][c] = dinv[r]*D -> overwrite XH/XL (T tiles)
        {
            const int r0 = m0 + g, r1 = r0 + 8;
            float d0 = s_dinv[r0], d1 = s_dinv[r1];
            #pragma unroll
            for (int nt = 0; nt < 4; nt++) {
                int c0 = n0 + nt * 8 + c0b;
                uint32_t lo, hi;
                hi = sp2(acc[nt][0] * d0, acc[nt][1] * d0, lo);
                *(uint32_t*)(sm + XH_O + r0 * ST + c0 * 2) = hi;
                *(uint32_t*)(sm + XL_O + r0 * ST + c0 * 2) = lo;
                hi = sp2(acc[nt][2] * d1, acc[nt][3] * d1, lo);
                *(uint32_t*)(sm + XH_O + r1 * ST + c0 * 2) = hi;
                *(uint32_t*)(sm + XL_O + r1 * ST + c0 * 2) = lo;
            }
        }
        __syncthreads();   // T visible

        #pragma unroll
        for (int i = 0; i < 4; i++) { acc[i][0]=acc[i][1]=acc[i][2]=acc[i][3]=0.f; }
        if (L < 2) {
            // gemm (transposed out): D[c][r] = Whi·(Thi+Tlo) + Wlo·Thi (tri-fused)
            gprod_tri(sb + WH_O + m0 * ST, sb + WL_O + m0 * ST,
                      sb + XH_O + n0 * ST, sb + XL_O + n0 * ST, lane, acc);
            __syncthreads();   // all T reads done
            // epi2: X^T[c][r] = relu(D + b[c]) * dinv[r]
            const int cA0 = m0 + g, cA1 = cA0 + 8;
            float bA0 = s_bias[cA0], bA1 = s_bias[cA1];
            #pragma unroll
            for (int nt = 0; nt < 4; nt++) {
                int r0 = n0 + nt * 8 + c0b;
                float da = s_dinv[r0], db = s_dinv[r0 + 1];
                uint32_t lo, hi;
                hi = sp2(fmaxf(acc[nt][0] + bA0, 0.f) * da,
                         fmaxf(acc[nt][1] + bA0, 0.f) * db, lo);
                *(uint32_t*)(sm + XH_O + cA0 * ST + r0 * 2) = hi;
                *(uint32_t*)(sm + XL_O + cA0 * ST + r0 * 2) = lo;
                hi = sp2(fmaxf(acc[nt][2] + bA1, 0.f) * da,
                         fmaxf(acc[nt][3] + bA1, 0.f) * db, lo);
                *(uint32_t*)(sm + XH_O + cA1 * ST + r0 * 2) = hi;
                *(uint32_t*)(sm + XL_O + cA1 * ST + r0 * 2) = lo;
            }
        } else {
            // gemm3: D[r][c] = (Thi+Tlo)·Whi + Thi·Wlo  (node-major h3, tri-fused)
            gprod_tri(sb + XH_O + m0 * ST, sb + XL_O + m0 * ST,
                      sb + WH_O + n0 * ST, sb + WL_O + n0 * ST, lane, acc);
            __syncthreads();
            // epi3: h3 = relu(D + b[c]); hi->ADJ, lo->XH; col-sums + server row
            const int r0 = m0 + g, r1 = r0 + 8;
            const bool srvlane = (m0 == 48) && (g == 7);   // r1 == 63
            float csA[4], csB[4];
            #pragma unroll
            for (int nt = 0; nt < 4; nt++) {
                int c0 = n0 + nt * 8 + c0b;
                float b0v = s_bias[c0], b1v = s_bias[c0 + 1];
                float v0 = fmaxf(acc[nt][0] + b0v, 0.f);
                float v1 = fmaxf(acc[nt][1] + b1v, 0.f);
                float v2 = fmaxf(acc[nt][2] + b0v, 0.f);
                float v3 = fmaxf(acc[nt][3] + b1v, 0.f);
                uint32_t lo, hi;
                hi = sp2(v0, v1, lo);
                *(uint32_t*)(sm + ADJ_O + r0 * ST + c0 * 2) = hi;
                *(uint32_t*)(sm + XH_O + r0 * ST + c0 * 2) = lo;
                hi = sp2(v2, v3, lo);
                *(uint32_t*)(sm + ADJ_O + r1 * ST + c0 * 2) = hi;
                *(uint32_t*)(sm + XH_O + r1 * ST + c0 * 2) = lo;
                csA[nt] = v0 + (srvlane ? 0.f : v2);
                csB[nt] = v1 + (srvlane ? 0.f : v3);
                if (srvlane) { s_h3s[c0] = v2; s_h3s[c0 + 1] = v3; }
            }
            #pragma unroll
            for (int off = 4; off < 32; off <<= 1) {
                #pragma unroll
                for (int nt = 0; nt < 4; nt++) {
                    csA[nt] += __shfl_xor_sync(0xffffffffu, csA[nt], off);
                    csB[nt] += __shfl_xor_sync(0xffffffffu, csB[nt], off);
                }
            }
            if (g == 0) {
                float* cs = s_cs + (m0 >> 4) * 64;
                #pragma unroll
                for (int nt = 0; nt < 4; nt++) {
                    int c0 = n0 + nt * 8 + c0b;
                    cs[c0] = csA[nt]; cs[c0 + 1] = csB[nt];
                }
            }
        }
        __syncthreads();
    }

    // ---- P1: mean from col-sums || cp.async Wf1^T half0 hi/lo + half1 hi + wf2 ----
    if (tid < 64) {
        s_mean[tid] = (s_cs[tid] + s_cs[64 + tid] + s_cs[128 + tid] + s_cs[192 + tid])
                      * (1.0f / 63.0f);
    } else {
        const unsigned char* hh = g_Wf1T[0];
        const unsigned char* hl = g_Wf1T[1];
        for (int i = tid - 64; i < 576; i += 192) {
            cpa16(sb + WH_O + i * 16, hh + i * 16);
            cpa16(sb + WL_O + i * 16, hl + i * 16);
            cpa16(sb + XL_O + i * 16, hh + 9216 + i * 16);   // half1 hi pre-staged
        }
        if (tid - 64 < 128) s_wf2[tid - 64] = Wf2[tid - 64];
    }
    CP_COMMIT();
    CP_WAIT0();
    __syncthreads();
    {   // u partials: 256 threads, half the k-range each (overlays s_cs)
        int m = tid & 127, half = tid >> 7, k0 = half * 32;
        float acc = 0.0f;
        #pragma unroll 4
        for (int k = k0; k < k0 + 32; k++) acc = fmaf(s_mean[k], Wf1[(64 + k) * 128 + m], acc);
        #pragma unroll 4
        for (int k = k0; k < k0 + 32; k++) acc = fmaf(s_h3s[k], Wf1[(128 + k) * 128 + m], acc);
        s_cs[tid] = acc;
    }
    __syncthreads();
    if (tid < 128) s_u[tid] = bf1[tid] + s_cs[tid] + s_cs[128 + tid];
    __syncthreads();

    // ---- head GEMM half 0 (B = WH/WL, tri-fused) ----
    float p0 = 0.f, p1 = 0.f;
    {
        float acc[4][4];
        #pragma unroll
        for (int i = 0; i < 4; i++) { acc[i][0]=acc[i][1]=acc[i][2]=acc[i][3]=0.f; }
        gprod_tri(sb + ADJ_O + m0 * ST, sb + XH_O + m0 * ST,
                  sb + WH_O + n0 * ST, sb + WL_O + n0 * ST, lane, acc);
        #pragma unroll
        for (int nt = 0; nt < 4; nt++) {
            int c0 = n0 + nt * 8 + c0b;
            float u0 = s_u[c0], u1 = s_u[c0 + 1], w0 = s_wf2[c0], w1 = s_wf2[c0 + 1];
            p0 = fmaf(fmaxf(acc[nt][0] + u0, 0.f), w0, p0);
            p0 = fmaf(fmaxf(acc[nt][1] + u1, 0.f), w1, p0);
            p1 = fmaf(fmaxf(acc[nt][2] + u0, 0.f), w0, p1);
            p1 = fmaf(fmaxf(acc[nt][3] + u1, 0.f), w1, p1);
        }
    }
    __syncthreads();   // WH reads done
    {   // cp.async half1 lo into WH (9KB)
        const unsigned char* hl = g_Wf1T[1] + 9216;
        for (int i = tid; i < 576; i += 256) cpa16(sb + WH_O + i * 16, hl + i * 16);
        CP_COMMIT();
        CP_WAIT0();
    }
    __syncthreads();
    // ---- head GEMM half 1 (B hi = XL pre-staged, lo = WH, tri-fused) ----
    {
        float acc[4][4];
        #pragma unroll
        for (int i = 0; i < 4; i++) { acc[i][0]=acc[i][1]=acc[i][2]=acc[i][3]=0.f; }
        gprod_tri(sb + ADJ_O + m0 * ST, sb + XH_O + m0 * ST,
                  sb + XL_O + n0 * ST, sb + WH_O + n0 * ST, lane, acc);
        #pragma unroll
        for (int nt = 0; nt < 4; nt++) {
            int c0 = 64 + n0 + nt * 8 + c0b;
            float u0 = s_u[c0], u1 = s_u[c0 + 1], w0 = s_wf2[c0], w1 = s_wf2[c0 + 1];
            p0 = fmaf(fmaxf(acc[nt][0] + u0, 0.f), w0, p0);
            p0 = fmaf(fmaxf(acc[nt][1] + u1, 0.f), w1, p0);
            p1 = fmaf(fmaxf(acc[nt][2] + u0, 0.f), w0, p1);
            p1 = fmaf(fmaxf(acc[nt][3] + u1, 0.f), w1, p1);
        }
    }
    p0 += __shfl_xor_sync(0xffffffffu, p0, 1); p0 += __shfl_xor_sync(0xffffffffu, p0, 2);
    p1 += __shfl_xor_sync(0xffffffffu, p1, 1); p1 += __shfl_xor_sync(0xffffffffu, p1, 2);
    if ((lane & 3) == 0) {
        s_part[ch2 * 64 + m0 + g] = p0;
        s_part[ch2 * 64 + m0 + g + 8] = p1;
    }
    __syncthreads();
    if (tid < 63) out[(size_t)b * 63 + tid] = s_part[tid] + s_part[64 + tid] + bf2[0];
}

extern "C" void kernel_launch(void* const* d_in, const int* in_sizes, int n_in,
                              void* d_out, int out_size)
{
    (void)in_sizes; (void)n_in; (void)out_size;
    cudaFuncSetAttribute(pgcn_main, cudaFuncAttributeMaxDynamicSharedMemorySize, SMEM_BYTES);
    pgcn_prep<<<64, 256>>>((const float*)d_in[7], (const float*)d_in[9],
                           (const float*)d_in[11], (const float*)d_in[13],
                           (const float*)d_in[3], (const float*)d_in[5]);
    pgcn_main<<<16384, 256, SMEM_BYTES>>>(
        (const float*)d_in[0],  (const float*)d_in[1],  (const float*)d_in[2],
        (const float*)d_in[4],  (const float*)d_in[6],  (const float*)d_in[8],
        (const float*)d_in[10], (const float*)d_in[12], (const float*)d_in[13],
        (const float*)d_in[14], (const float*)d_in[15], (const float*)d_in[16],
        (float*)d_out);
}

// round 17
// speedup vs baseline: 1.1403x; 1.0162x over previous
#include <cuda_runtime.h>
#include <cuda_bf16.h>
#include <cstdint>

#define ST 144                  // row stride bytes (72 bf16): bank-rotating, 16B-aligned
#define ADJ_O 0                 // adjacency -> h3 hi
#define XH_O  9216              // obs fp32 scratch -> X^T hi / T hi / h3 lo
#define XL_O  18432             // X^T lo / T lo / head: Wf1^T half1 hi
#define WH_O  27648             // W^T hi (emb: obs hi cols0-31 + embW hi cols64-127; head: Wf1^T half0 hi -> half1 lo)
#define WL_O  36864             // W^T lo
#define MLO_O  46080
#define MHI_O  46336
#define DINV_O 46592
#define BIAS_O 46848
#define U_O    47104
#define WF2_O  47616
#define MEAN_O 48128
#define H3S_O  48384
#define PART_O 48640            // float[2][64]
#define CS_O   49152            // emb biases (bd|bs) -> col-sums -> u partials
#define SMEM_BYTES 50176

static __device__ __align__(16) unsigned char g_WT[3][2][9216];   // W_L^T [n][k] hi/lo
static __device__ __align__(16) unsigned char g_Wf1T[2][18432];   // Wf1_dev^T [m][k] hi/lo
static __device__ __align__(16) unsigned char g_embWT[2][4096];   // combined emb W^T [c][k<32] hi/lo (64B rows)

__device__ __forceinline__ uint32_t smem_u32(const void* p) {
    uint32_t a;
    asm("{ .reg .u64 t; cvta.to.shared.u64 t, %1; cvt.u32.u64 %0, t; }" : "=r"(a) : "l"(p));
    return a;
}
__device__ __forceinline__ void cpa16(uint32_t dst, const void* src) {
    asm volatile("cp.async.cg.shared.global [%0], [%1], 16;" :: "r"(dst), "l"(src));
}
#define CP_COMMIT() asm volatile("cp.async.commit_group;" ::: "memory")
#define CP_WAIT0()  asm volatile("cp.async.wait_group 0;" ::: "memory")

__device__ __forceinline__ void ldsm4(uint32_t addr, uint32_t* r) {
    asm volatile("ldmatrix.sync.aligned.m8n8.x4.shared.b16 {%0,%1,%2,%3}, [%4];"
                 : "=r"(r[0]), "=r"(r[1]), "=r"(r[2]), "=r"(r[3]) : "r"(addr));
}
__device__ __forceinline__ void mma16816(float* d, const uint32_t* a, const uint32_t* b) {
    asm volatile("mma.sync.aligned.m16n8k16.row.col.f32.bf16.bf16.f32 "
        "{%0,%1,%2,%3}, {%4,%5,%6,%7}, {%8,%9}, {%0,%1,%2,%3};"
        : "+f"(d[0]), "+f"(d[1]), "+f"(d[2]), "+f"(d[3])
        : "r"(a[0]), "r"(a[1]), "r"(a[2]), "r"(a[3]), "r"(b[0]), "r"(b[1]));
}
__device__ __forceinline__ void sp1(float v, uint16_t& h, uint16_t& l) {
    __nv_bfloat16 hb = __float2bfloat16(v);
    __nv_bfloat16 lb = __float2bfloat16(v - __bfloat162float(hb));
    h = __bfloat16_as_ushort(hb); l = __bfloat16_as_ushort(lb);
}
__device__ __forceinline__ uint32_t sp2(float a, float b, uint32_t& lo) {
    uint32_t hi;
    asm("cvt.rn.bf16x2.f32 %0, %1, %2;" : "=r"(hi) : "f"(b), "f"(a));
    float ha = __uint_as_float(hi << 16);
    float hb = __uint_as_float(hi & 0xffff0000u);
    asm("cvt.rn.bf16x2.f32 %0, %1, %2;" : "=r"(lo) : "f"(b - hb), "f"(a - ha));
    return hi;
}
// acc += A@B1^T + A@B2^T (A loaded once)
__device__ __forceinline__ void gprod_dualB(uint32_t aB, uint32_t b1B, uint32_t b2B,
                                            int lane, float (*acc)[4]) {
    const int arow = lane & 15, acol = (lane >> 4) << 3;
    const int brow = (lane & 7) + ((lane & 16) >> 1), bcol = lane & 8;
    #pragma unroll
    for (int kk = 0; kk < 64; kk += 16) {
        uint32_t a[4]; ldsm4(aB + arow * ST + (kk + acol) * 2, a);
        #pragma unroll
        for (int nt = 0; nt < 2; nt++) {
            uint32_t bf1[4], bf2[4];
            ldsm4(b1B + (nt * 16 + brow) * ST + (kk + bcol) * 2, bf1);
            ldsm4(b2B + (nt * 16 + brow) * ST + (kk + bcol) * 2, bf2);
            mma16816(acc[nt * 2], a, bf1);
            mma16816(acc[nt * 2 + 1], a, bf1 + 2);
            mma16816(acc[nt * 2], a, bf2);
            mma16816(acc[nt * 2 + 1], a, bf2 + 2);
        }
    }
}
// acc += A1@B1^T + A1@B2^T + A2@B1^T — fragments loaded once; K=64
__device__ __forceinline__ void gprod_tri(uint32_t a1B, uint32_t a2B,
                                          uint32_t b1B, uint32_t b2B,
                                          int lane, float (*acc)[4]) {
    const int arow = lane & 15, acol = (lane >> 4) << 3;
    const int brow = (lane & 7) + ((lane & 16) >> 1), bcol = lane & 8;
    #pragma unroll
    for (int kk = 0; kk < 64; kk += 16) {
        uint32_t a0[4], a1[4];
        ldsm4(a1B + arow * ST + (kk + acol) * 2, a0);
        ldsm4(a2B + arow * ST + (kk + acol) * 2, a1);
        #pragma unroll
        for (int nt = 0; nt < 2; nt++) {
            uint32_t bf1[4], bf2[4];
            ldsm4(b1B + (nt * 16 + brow) * ST + (kk + bcol) * 2, bf1);
            ldsm4(b2B + (nt * 16 + brow) * ST + (kk + bcol) * 2, bf2);
            mma16816(acc[nt * 2], a0, bf1);
            mma16816(acc[nt * 2 + 1], a0, bf1 + 2);
            mma16816(acc[nt * 2], a1, bf1);
            mma16816(acc[nt * 2 + 1], a1, bf1 + 2);
            mma16816(acc[nt * 2], a0, bf2);
            mma16816(acc[nt * 2 + 1], a0, bf2 + 2);
        }
    }
}
// same, K=32 (embedding)
__device__ __forceinline__ void gprod_tri32(uint32_t a1B, uint32_t a2B,
                                            uint32_t b1B, uint32_t b2B,
                                            int lane, float (*acc)[4]) {
    const int arow = lane & 15, acol = (lane >> 4) << 3;
    const int brow = (lane & 7) + ((lane & 16) >> 1), bcol = lane & 8;
    #pragma unroll
    for (int kk = 0; kk < 32; kk += 16) {
        uint32_t a0[4], a1[4];
        ldsm4(a1B + arow * ST + (kk + acol) * 2, a0);
        ldsm4(a2B + arow * ST + (kk + acol) * 2, a1);
        #pragma unroll
        for (int nt = 0; nt < 2; nt++) {
            uint32_t bf1[4], bf2[4];
            ldsm4(b1B + (nt * 16 + brow) * ST + (kk + bcol) * 2, bf1);
            ldsm4(b2B + (nt * 16 + brow) * ST + (kk + bcol) * 2, bf2);
            mma16816(acc[nt * 2], a0, bf1);
            mma16816(acc[nt * 2 + 1], a0, bf1 + 2);
            mma16816(acc[nt * 2], a1, bf1);
            mma16816(acc[nt * 2 + 1], a1, bf1 + 2);
            mma16816(acc[nt * 2], a0, bf2);
            mma16816(acc[nt * 2 + 1], a0, bf2 + 2);
        }
    }
}

__global__ void pgcn_prep(const float* __restrict__ W1, const float* __restrict__ W2,
                          const float* __restrict__ W3, const float* __restrict__ Wf1,
                          const float* __restrict__ W_dev, const float* __restrict__ W_srv) {
    const float* Ws[3] = {W1, W2, W3};
    int gt = blockIdx.x * blockDim.x + threadIdx.x, nth = gridDim.x * blockDim.x;
    for (int L = 0; L < 3; L++)
        for (int i = gt; i < 4096; i += nth) {
            int n = i >> 6, k = i & 63;
            uint16_t h, l; sp1(Ws[L][k * 64 + n], h, l);
            *(uint16_t*)(g_WT[L][0] + n * ST + k * 2) = h;
            *(uint16_t*)(g_WT[L][1] + n * ST + k * 2) = l;
        }
    for (int i = gt; i < 8192; i += nth) {
        int m = i >> 6, k = i & 63;
        uint16_t h, l; sp1(Wf1[k * 128 + m], h, l);
        *(uint16_t*)(g_Wf1T[0] + m * ST + k * 2) = h;
        *(uint16_t*)(g_Wf1T[1] + m * ST + k * 2) = l;
    }
    for (int i = gt; i < 2048; i += nth) {
        int c = i >> 5, k = i & 31;
        float v = (k < 14) ? W_dev[k * 64 + c] : (k < 17 ? W_srv[(k - 14) * 64 + c] : 0.0f);
        uint16_t h, l; sp1(v, h, l);
        *(uint16_t*)(g_embWT[0] + c * 64 + k * 2) = h;
        *(uint16_t*)(g_embWT[1] + c * 64 + k * 2) = l;
    }
}

__global__ __launch_bounds__(256, 4)
void pgcn_main(const float* __restrict__ dev_obs, const float* __restrict__ srv_obs,
               const float* __restrict__ adj,
               const float* __restrict__ b_dev, const float* __restrict__ b_srv,
               const float* __restrict__ b1, const float* __restrict__ b2,
               const float* __restrict__ b3,
               const float* __restrict__ Wf1, const float* __restrict__ bf1,
               const float* __restrict__ Wf2, const float* __restrict__ bf2,
               float* __restrict__ out)
{
    extern __shared__ __align__(16) unsigned char sm[];
    const uint32_t sb = smem_u32(sm);
    unsigned* s_mlo = (unsigned*)(sm + MLO_O);
    unsigned* s_mhi = (unsigned*)(sm + MHI_O);
    float* s_dinv = (float*)(sm + DINV_O);
    float* s_bias = (float*)(sm + BIAS_O);
    float* s_u    = (float*)(sm + U_O);
    float* s_wf2  = (float*)(sm + WF2_O);
    float* s_mean = (float*)(sm + MEAN_O);
    float* s_h3s  = (float*)(sm + H3S_O);
    float* s_part = (float*)(sm + PART_O);
    float* s_cs   = (float*)(sm + CS_O);
    float* s_scr  = (float*)(sm + XH_O);   // obs fp32 scratch (pre-embedding only)

    const int tid = threadIdx.x, lane = tid & 31, wid = tid >> 5;
    const int b = blockIdx.x;
    const int m0 = (wid & 3) * 16, ch2 = wid >> 2, n0 = ch2 * 32;
    const int g = lane >> 2, c0b = (lane & 3) * 2;

    // ---- Phase A: coalesced obs -> scratch; cp.async embW; biases; masks + dinv ----
    for (int i = tid; i < 882; i += 256) s_scr[i] = dev_obs[(size_t)b * 882 + i];
    if (tid < 3) s_scr[882 + tid] = srv_obs[b * 3 + tid];
    if (tid >= 64 && tid < 128) {
        for (int i = tid - 64; i < 256; i += 64) {
            int row = i >> 2, q = i & 3;
            cpa16(sb + WH_O + row * ST + 64 + q * 16, g_embWT[0] + row * 64 + q * 16);
            cpa16(sb + WL_O + row * ST + 64 + q * 16, g_embWT[1] + row * 64 + q * 16);
        }
    } else if (tid >= 128 && tid < 192) {
        int i = tid - 128;
        s_cs[i] = b_dev[i];
        s_cs[64 + i] = b_srv[i];
    }
    CP_COMMIT();
    {
        const float* ar = adj + (size_t)b * 4096;
        for (int r = wid; r < 64; r += 8) {
            unsigned a0 = __ballot_sync(0xffffffffu, ar[r * 64 + lane] != 0.0f);
            unsigned a1 = __ballot_sync(0xffffffffu, ar[r * 64 + 32 + lane] != 0.0f);
            if (lane == 0) {
                s_mlo[r] = a0; s_mhi[r] = a1;
                s_dinv[r] = rsqrtf(fmaxf((float)(__popc(a0) + __popc(a1)), 1.0f));
            }
        }
    }
    __syncthreads();

    // ---- Phase B: obs bf16 tiles (128 threads, from scratch) + adjacency bf16 tile ----
    if (tid < 128) {
        int n = tid >> 1, jh = (tid & 1) * 8;
        #pragma unroll
        for (int j = 0; j < 8; j++) {
            int k0 = (jh + j) * 2;
            float va, vb;
            if (n < 63) {
                va = (k0 < 14)     ? s_scr[n * 14 + k0]     : 0.f;
                vb = (k0 + 1 < 14) ? s_scr[n * 14 + k0 + 1] : 0.f;
            } else {
                va = (k0 >= 14 && k0 < 17)     ? s_scr[882 + k0 - 14] : 0.f;
                vb = (k0 + 1 >= 14 && k0 + 1 < 17) ? s_scr[882 + k0 - 13] : 0.f;
            }
            uint32_t lo, hi = sp2(va, vb, lo);
            *(uint32_t*)(sm + WH_O + n * ST + (jh + j) * 4) = hi;
            *(uint32_t*)(sm + WL_O + n * ST + (jh + j) * 4) = lo;
        }
    }
    for (int i = tid; i < 512; i += 256) {
        int r = i >> 3, chk = i & 7;
        unsigned byte8 = ((chk < 4 ? s_mlo[r] : s_mhi[r]) >> ((chk & 3) * 8)) & 0xFF;
        uint4 v; uint32_t* vp = (uint32_t*)&v;
        #pragma unroll
        for (int j = 0; j < 4; j++) {
            unsigned b2 = (byte8 >> (2 * j)) & 3;
            vp[j] = ((b2 & 1) ? 0x3F80u : 0u) | ((b2 & 2) ? 0x3F800000u : 0u);
        }
        *(uint4*)(sm + ADJ_O + r * ST + chk * 16) = v;
    }
    CP_WAIT0();
    __syncthreads();

    // ---- embedding GEMM: D[c][n] = embW @ obs^T (tri-fused split, K=32) ----
    {
        float acc[4][4];
        #pragma unroll
        for (int i = 0; i < 4; i++) { acc[i][0]=acc[i][1]=acc[i][2]=acc[i][3]=0.f; }
        gprod_tri32(sb + WH_O + 64 + m0 * ST, sb + WL_O + 64 + m0 * ST,
                    sb + WH_O + n0 * ST, sb + WL_O + n0 * ST, lane, acc);
        const int cA0 = m0 + g, cA1 = cA0 + 8;
        float bd0 = s_cs[cA0], bd1 = s_cs[cA1];
        float bs0 = s_cs[64 + cA0], bs1 = s_cs[64 + cA1];
        #pragma unroll
        for (int nt = 0; nt < 4; nt++) {
            int r0 = n0 + nt * 8 + c0b;
            float da = s_dinv[r0], db = s_dinv[r0 + 1];
            float bb0a = (r0 == 63) ? bs0 : bd0, bb0b = (r0 + 1 == 63) ? bs0 : bd0;
            float bb1a = (r0 == 63) ? bs1 : bd1, bb1b = (r0 + 1 == 63) ? bs1 : bd1;
            uint32_t lo, hi;
            hi = sp2(fmaxf(acc[nt][0] + bb0a, 0.f) * da,
                     fmaxf(acc[nt][1] + bb0b, 0.f) * db, lo);
            *(uint32_t*)(sm + XH_O + cA0 * ST + r0 * 2) = hi;
            *(uint32_t*)(sm + XL_O + cA0 * ST + r0 * 2) = lo;
            hi = sp2(fmaxf(acc[nt][2] + bb1a, 0.f) * da,
                     fmaxf(acc[nt][3] + bb1b, 0.f) * db, lo);
            *(uint32_t*)(sm + XH_O + cA1 * ST + r0 * 2) = hi;
            *(uint32_t*)(sm + XL_O + cA1 * ST + r0 * 2) = lo;
        }
    }
    __syncthreads();

    // ---- 3 GCN layers ----
    #pragma unroll 1
    for (int L = 0; L < 3; L++) {
        {   // async-stage W^T hi/lo (completes under the agg gprods) + bias
            const unsigned char* wh = g_WT[L][0];
            const unsigned char* wl = g_WT[L][1];
            for (int i = tid; i < 576; i += 256) {
                cpa16(sb + WH_O + i * 16, wh + i * 16);
                cpa16(sb + WL_O + i * 16, wl + i * 16);
            }
            CP_COMMIT();
            const float* bl = (L == 0) ? b1 : (L == 1) ? b2 : b3;
            if (tid < 64) s_bias[tid] = bl[tid];
        }
        // aggregation: D[r][c] = Adj @ (XH + XL)^T
        float acc[4][4];
        #pragma unroll
        for (int i = 0; i < 4; i++) { acc[i][0]=acc[i][1]=acc[i][2]=acc[i][3]=0.f; }
        gprod_dualB(sb + ADJ_O + m0 * ST, sb + XH_O + n0 * ST, sb + XL_O + n0 * ST, lane, acc);
        CP_WAIT0();
        __syncthreads();   // all X reads done; W staged

        // epi1: T[r][c] = dinv[r]*D -> overwrite XH/XL (T tiles)
        {
            const int r0 = m0 + g, r1 = r0 + 8;
            float d0 = s_dinv[r0], d1 = s_dinv[r1];
            #pragma unroll
            for (int nt = 0; nt < 4; nt++) {
                int c0 = n0 + nt * 8 + c0b;
                uint32_t lo, hi;
                hi = sp2(acc[nt][0] * d0, acc[nt][1] * d0, lo);
                *(uint32_t*)(sm + XH_O + r0 * ST + c0 * 2) = hi;
                *(uint32_t*)(sm + XL_O + r0 * ST + c0 * 2) = lo;
                hi = sp2(acc[nt][2] * d1, acc[nt][3] * d1, lo);
                *(uint32_t*)(sm + XH_O + r1 * ST + c0 * 2) = hi;
                *(uint32_t*)(sm + XL_O + r1 * ST + c0 * 2) = lo;
            }
        }
        __syncthreads();   // T visible

        #pragma unroll
        for (int i = 0; i < 4; i++) { acc[i][0]=acc[i][1]=acc[i][2]=acc[i][3]=0.f; }
        if (L < 2) {
            // gemm (transposed out): D[c][r] = Whi·(Thi+Tlo) + Wlo·Thi (tri-fused)
            gprod_tri(sb + WH_O + m0 * ST, sb + WL_O + m0 * ST,
                      sb + XH_O + n0 * ST, sb + XL_O + n0 * ST, lane, acc);
            __syncthreads();   // all T reads done
            // epi2: X^T[c][r] = relu(D + b[c]) * dinv[r]
            const int cA0 = m0 + g, cA1 = cA0 + 8;
            float bA0 = s_bias[cA0], bA1 = s_bias[cA1];
            #pragma unroll
            for (int nt = 0; nt < 4; nt++) {
                int r0 = n0 + nt * 8 + c0b;
                float da = s_dinv[r0], db = s_dinv[r0 + 1];
                uint32_t lo, hi;
                hi = sp2(fmaxf(acc[nt][0] + bA0, 0.f) * da,
                         fmaxf(acc[nt][1] + bA0, 0.f) * db, lo);
                *(uint32_t*)(sm + XH_O + cA0 * ST + r0 * 2) = hi;
                *(uint32_t*)(sm + XL_O + cA0 * ST + r0 * 2) = lo;
                hi = sp2(fmaxf(acc[nt][2] + bA1, 0.f) * da,
                         fmaxf(acc[nt][3] + bA1, 0.f) * db, lo);
                *(uint32_t*)(sm + XH_O + cA1 * ST + r0 * 2) = hi;
                *(uint32_t*)(sm + XL_O + cA1 * ST + r0 * 2) = lo;
            }
        } else {
            // gemm3: D[r][c] = (Thi+Tlo)·Whi + Thi·Wlo  (node-major h3, tri-fused)
            gprod_tri(sb + XH_O + m0 * ST, sb + XL_O + m0 * ST,
                      sb + WH_O + n0 * ST, sb + WL_O + n0 * ST, lane, acc);
            __syncthreads();
            // epi3: h3 = relu(D + b[c]); hi->ADJ, lo->XH; col-sums + server row
            const int r0 = m0 + g, r1 = r0 + 8;
            const bool srvlane = (m0 == 48) && (g == 7);   // r1 == 63
            float csA[4], csB[4];
            #pragma unroll
            for (int nt = 0; nt < 4; nt++) {
                int c0 = n0 + nt * 8 + c0b;
                float b0v = s_bias[c0], b1v = s_bias[c0 + 1];
                float v0 = fmaxf(acc[nt][0] + b0v, 0.f);
                float v1 = fmaxf(acc[nt][1] + b1v, 0.f);
                float v2 = fmaxf(acc[nt][2] + b0v, 0.f);
                float v3 = fmaxf(acc[nt][3] + b1v, 0.f);
                uint32_t lo, hi;
                hi = sp2(v0, v1, lo);
                *(uint32_t*)(sm + ADJ_O + r0 * ST + c0 * 2) = hi;
                *(uint32_t*)(sm + XH_O + r0 * ST + c0 * 2) = lo;
                hi = sp2(v2, v3, lo);
                *(uint32_t*)(sm + ADJ_O + r1 * ST + c0 * 2) = hi;
                *(uint32_t*)(sm + XH_O + r1 * ST + c0 * 2) = lo;
                csA[nt] = v0 + (srvlane ? 0.f : v2);
                csB[nt] = v1 + (srvlane ? 0.f : v3);
                if (srvlane) { s_h3s[c0] = v2; s_h3s[c0 + 1] = v3; }
            }
            #pragma unroll
            for (int off = 4; off < 32; off <<= 1) {
                #pragma unroll
                for (int nt = 0; nt < 4; nt++) {
                    csA[nt] += __shfl_xor_sync(0xffffffffu, csA[nt], off);
                    csB[nt] += __shfl_xor_sync(0xffffffffu, csB[nt], off);
                }
            }
            if (g == 0) {
                float* cs = s_cs + (m0 >> 4) * 64;
                #pragma unroll
                for (int nt = 0; nt < 4; nt++) {
                    int c0 = n0 + nt * 8 + c0b;
                    cs[c0] = csA[nt]; cs[c0 + 1] = csB[nt];
                }
            }
        }
        __syncthreads();
    }

    // ---- P1: mean from col-sums || cp.async Wf1^T half0 hi/lo + half1 hi + wf2 ----
    if (tid < 64) {
        s_mean[tid] = (s_cs[tid] + s_cs[64 + tid] + s_cs[128 + tid] + s_cs[192 + tid])
                      * (1.0f / 63.0f);
    } else {
        const unsigned char* hh = g_Wf1T[0];
        const unsigned char* hl = g_Wf1T[1];
        for (int i = tid - 64; i < 576; i += 192) {
            cpa16(sb + WH_O + i * 16, hh + i * 16);
            cpa16(sb + WL_O + i * 16, hl + i * 16);
            cpa16(sb + XL_O + i * 16, hh + 9216 + i * 16);   // half1 hi pre-staged
        }
        if (tid - 64 < 128) s_wf2[tid - 64] = Wf2[tid - 64];
    }
    CP_COMMIT();
    CP_WAIT0();
    __syncthreads();
    {   // u partials: 256 threads, half k-range each, 4 accumulators (overlays s_cs)
        int m = tid & 127, half = tid >> 7, k0 = half * 32;
        float a0 = 0.f, a1 = 0.f, a2 = 0.f, a3 = 0.f;
        #pragma unroll
        for (int k = k0; k < k0 + 32; k += 4) {
            a0 = fmaf(s_mean[k],     Wf1[(64 + k) * 128 + m], a0);
            a1 = fmaf(s_mean[k + 1], Wf1[(65 + k) * 128 + m], a1);
            a2 = fmaf(s_mean[k + 2], Wf1[(66 + k) * 128 + m], a2);
            a3 = fmaf(s_mean[k + 3], Wf1[(67 + k) * 128 + m], a3);
        }
        #pragma unroll
        for (int k = k0; k < k0 + 32; k += 4) {
            a0 = fmaf(s_h3s[k],     Wf1[(128 + k) * 128 + m], a0);
            a1 = fmaf(s_h3s[k + 1], Wf1[(129 + k) * 128 + m], a1);
            a2 = fmaf(s_h3s[k + 2], Wf1[(130 + k) * 128 + m], a2);
            a3 = fmaf(s_h3s[k + 3], Wf1[(131 + k) * 128 + m], a3);
        }
        s_cs[tid] = (a0 + a1) + (a2 + a3);
    }
    __syncthreads();
    if (tid < 128) s_u[tid] = bf1[tid] + s_cs[tid] + s_cs[128 + tid];
    __syncthreads();

    // ---- head GEMM half 0 (B = WH/WL, tri-fused) ----
    float p0 = 0.f, p1 = 0.f;
    float h0acc[4][4];
    {
        #pragma unroll
        for (int i = 0; i < 4; i++) { h0acc[i][0]=h0acc[i][1]=h0acc[i][2]=h0acc[i][3]=0.f; }
        gprod_tri(sb + ADJ_O + m0 * ST, sb + XH_O + m0 * ST,
                  sb + WH_O + n0 * ST, sb + WL_O + n0 * ST, lane, h0acc);
    }
    __syncthreads();   // WH reads done (all warps)
    {   // issue cp.async half1-lo into WH, then overlap the half0 epilogue with it
        const unsigned char* hl = g_Wf1T[1] + 9216;
        for (int i = tid; i < 576; i += 256) cpa16(sb + WH_O + i * 16, hl + i * 16);
        CP_COMMIT();
    }
    #pragma unroll
    for (int nt = 0; nt < 4; nt++) {
        int c0 = n0 + nt * 8 + c0b;
        float u0 = s_u[c0], u1 = s_u[c0 + 1], w0 = s_wf2[c0], w1 = s_wf2[c0 + 1];
        p0 = fmaf(fmaxf(h0acc[nt][0] + u0, 0.f), w0, p0);
        p0 = fmaf(fmaxf(h0acc[nt][1] + u1, 0.f), w1, p0);
        p1 = fmaf(fmaxf(h0acc[nt][2] + u0, 0.f), w0, p1);
        p1 = fmaf(fmaxf(h0acc[nt][3] + u1, 0.f), w1, p1);
    }
    CP_WAIT0();
    __syncthreads();
    // ---- head GEMM half 1 (B hi = XL pre-staged, lo = WH, tri-fused) ----
    {
        float acc[4][4];
        #pragma unroll
        for (int i = 0; i < 4; i++) { acc[i][0]=acc[i][1]=acc[i][2]=acc[i][3]=0.f; }
        gprod_tri(sb + ADJ_O + m0 * ST, sb + XH_O + m0 * ST,
                  sb + XL_O + n0 * ST, sb + WH_O + n0 * ST, lane, acc);
        #pragma unroll
        for (int nt = 0; nt < 4; nt++) {
            int c0 = 64 + n0 + nt * 8 + c0b;
            float u0 = s_u[c0], u1 = s_u[c0 + 1], w0 = s_wf2[c0], w1 = s_wf2[c0 + 1];
            p0 = fmaf(fmaxf(acc[nt][0] + u0, 0.f), w0, p0);
            p0 = fmaf(fmaxf(acc[nt][1] + u1, 0.f), w1, p0);
            p1 = fmaf(fmaxf(acc[nt][2] + u0, 0.f), w0, p1);
            p1 = fmaf(fmaxf(acc[nt][3] + u1, 0.f), w1, p1);
        }
    }
    p0 += __shfl_xor_sync(0xffffffffu, p0, 1); p0 += __shfl_xor_sync(0xffffffffu, p0, 2);
    p1 += __shfl_xor_sync(0xffffffffu, p1, 1); p1 += __shfl_xor_sync(0xffffffffu, p1, 2);
    if ((lane & 3) == 0) {
        s_part[ch2 * 64 + m0 + g] = p0;
        s_part[ch2 * 64 + m0 + g + 8] = p1;
    }
    __syncthreads();
    if (tid < 63) out[(size_t)b * 63 + tid] = s_part[tid] + s_part[64 + tid] + bf2[0];
}

extern "C" void kernel_launch(void* const* d_in, const int* in_sizes, int n_in,
                              void* d_out, int out_size)
{
    (void)in_sizes; (void)n_in; (void)out_size;
    cudaFuncSetAttribute(pgcn_main, cudaFuncAttributeMaxDynamicSharedMemorySize, SMEM_BYTES);
    pgcn_prep<<<64, 256>>>((const float*)d_in[7], (const float*)d_in[9],
                           (const float*)d_in[11], (const float*)d_in[13],
                           (const float*)d_in[3], (const float*)d_in[5]);
    pgcn_main<<<16384, 256, SMEM_BYTES>>>(
        (const float*)d_in[0],  (const float*)d_in[1],  (const float*)d_in[2],
        (const float*)d_in[4],  (const float*)d_in[6],  (const float*)d_in[8],
        (const float*)d_in[10], (const float*)d_in[12], (const float*)d_in[13],
        (const float*)d_in[14], (const float*)d_in[15], (const float*)d_in[16],
        (float*)d_out);
}